// round 14
// baseline (speedup 1.0000x reference)
#include <cuda_runtime.h>
#include <cuda_fp16.h>
#include <stdint.h>
#include <math.h>

// Problem constants
#define NN 8192      // nodes
#define TT 64        // timesteps
#define DIN 64       // input dim
#define RR 256       // reservoir dim
#define EE 131072    // edges
#define DOUT 64
#define CATD 1024    // (K+1)*R

// persistent step kernel tiling: CTA = 32 rows x 256 cols, K=320 in 10 chunks of 32.
// fp16 2-product scheme: A (x|h) single fp16; B (weights) split hi/lo fp16.
// 256 threads / 8 warps (2m x 4n, warp tile 16x64); TWO CTAs per SM (independent
// barrier domains overlap each other's sync/drain stalls).
#define MTILE 32
#define AROW 80                      // smem bytes per 32-fp16 row (64B data + 16B pad)
#define ACH  (MTILE * AROW)          // 2560 B  (one A chunk)
#define AREG (10 * ACH)              // 25600 B resident A region
#define BTYPE (256 * AROW)           // 20480 B (one chunk, one type)
#define BBUF (2 * BTYPE)             // 40960 B per slot (hi+lo)
#define NSLOT 2
#define STEP_SMEM (AREG + NSLOT * BBUF)  // 107520 B  (x2 CTAs = 215040 < 227K cap)

// ---------------- device scratch (static allocations only) ----------------
__device__ __align__(16) __half d_Bhi[RR * 320];   // [Win|Wres] fp16 hi, [256][320]
__device__ __align__(16) __half d_Blo[RR * 320];   // fp16 lo (B - hi)
__device__ unsigned d_bitmap[NN * (NN / 32)];
__device__ int      d_deg[NN];
__device__ int      d_rowptr[NN + 1];
__device__ int      d_col[2 * EE];
__device__ float    d_dinv[NN];
__device__ float    d_cat[NN * CATD];
__device__ int      d_is64;

// ================= PTX helpers (sm_80-compatible only) =================
__device__ __forceinline__ uint32_t s2u(const void* p) {
    uint32_t a;
    asm("{ .reg .u64 t; cvta.to.shared.u64 t, %1; cvt.u32.u64 %0, t; }" : "=r"(a) : "l"(p));
    return a;
}
#define LDSM4(r, addr) \
    asm volatile("ldmatrix.sync.aligned.m8n8.x4.shared.b16 {%0,%1,%2,%3}, [%4];" \
        : "=r"((r)[0]), "=r"((r)[1]), "=r"((r)[2]), "=r"((r)[3]) : "r"(addr))

#define MMA16816(d, a, b0, b1) \
    asm volatile("mma.sync.aligned.m16n8k16.row.col.f32.f16.f16.f32 " \
        "{%0,%1,%2,%3}, {%4,%5,%6,%7}, {%8,%9}, {%0,%1,%2,%3};" \
        : "+f"((d)[0]), "+f"((d)[1]), "+f"((d)[2]), "+f"((d)[3]) \
        : "r"((a)[0]), "r"((a)[1]), "r"((a)[2]), "r"((a)[3]), "r"(b0), "r"(b1))

#define CPA16(dst, src) \
    asm volatile("cp.async.cg.shared.global [%0], [%1], 16;" :: "r"(dst), "l"(src) : "memory")
#define CP_COMMIT asm volatile("cp.async.commit_group;" ::: "memory")
#define CP_WAIT0  asm volatile("cp.async.wait_group 0;" ::: "memory")

__device__ __forceinline__ float ftanh(float v) {
    float a = fabsf(v);
    float e = __expf(-2.0f * a);
    float r = __fdividef(1.0f - e, 1.0f + e);
    return copysignf(r, v);
}

// ---------------- dtype detection for edge_index (int32 vs int64) ----------------
__global__ void detect_kernel(const unsigned* __restrict__ w) {
    if (threadIdx.x == 0) {
        int f = 1;
        for (int i = 0; i < 64; i++) {
            if (w[2 * i + 1] != 0u) { f = 0; break; }
        }
        d_is64 = f;
    }
}

// ---------------- zero bitmap ----------------
__global__ void zero_kernel() {
    int i = blockIdx.x * blockDim.x + threadIdx.x;  // 2097152 threads
    d_bitmap[i] = 0u;
}

// ---------------- weight conversion to fp16 hi/lo ----------------
__global__ void wconv_kernel(const float* __restrict__ Win, const float* __restrict__ Wres) {
    int i = blockIdx.x * blockDim.x + threadIdx.x;
    if (i >= 256 * 320) return;
    int r = i / 320, k = i % 320;
    float v = (k < DIN) ? Win[r * DIN + k] : Wres[r * RR + (k - DIN)];
    __half h = __float2half(v);
    d_Bhi[i] = h;
    d_Blo[i] = __float2half(v - __half2float(h));
}

// ---------------- build binary adjacency bitmap ----------------
__global__ void pass1_kernel(const void* __restrict__ ei) {
    int i = blockIdx.x * blockDim.x + threadIdx.x;
    if (i >= 2 * EE) return;
    int u, v;
    if (d_is64) {
        const long long* p = (const long long*)ei;
        if (i < EE) { u = (int)p[i]; v = (int)p[EE + i]; }
        else        { u = (int)p[i]; v = (int)p[i - EE]; }
    } else {
        const int* p = (const int*)ei;
        if (i < EE) { u = p[i]; v = p[EE + i]; }
        else        { u = p[i]; v = p[i - EE]; }
    }
    atomicOr(&d_bitmap[(u << 8) + (v >> 5)], 1u << (v & 31));
}

// ---------------- degree + dinv ----------------
__global__ void degdinv_kernel() {
    int gw = (blockIdx.x * blockDim.x + threadIdx.x) >> 5;
    int lane = threadIdx.x & 31;
    if (gw >= NN) return;
    const unsigned* row = d_bitmap + gw * 256;
    int c = 0;
#pragma unroll
    for (int j = 0; j < 8; j++) c += __popc(row[lane * 8 + j]);
#pragma unroll
    for (int o = 16; o; o >>= 1) c += __shfl_xor_sync(0xffffffffu, c, o);
    if (lane == 0) {
        d_deg[gw] = c;
        d_dinv[gw] = (c > 0) ? fminf(1e6f, 1.0f / sqrtf((float)c)) : 0.0f;
    }
}

// ---------------- exclusive scan -> rowptr ----------------
__global__ void scan_kernel() {
    __shared__ int s[1024];
    int tid = threadIdx.x;
    int loc[8]; int sum = 0;
#pragma unroll
    for (int j = 0; j < 8; j++) { loc[j] = d_deg[tid * 8 + j]; sum += loc[j]; }
    s[tid] = sum;
    __syncthreads();
    for (int off = 1; off < 1024; off <<= 1) {
        int t = 0;
        if (tid >= off) t = s[tid - off];
        __syncthreads();
        s[tid] += t;
        __syncthreads();
    }
    int run = (tid == 0) ? 0 : s[tid - 1];
    if (tid == 0) d_rowptr[0] = 0;
#pragma unroll
    for (int j = 0; j < 8; j++) { run += loc[j]; d_rowptr[tid * 8 + j + 1] = run; }
}

// ---------------- extract CSR cols ----------------
__global__ void extract_kernel() {
    int gw = (blockIdx.x * blockDim.x + threadIdx.x) >> 5;
    int lane = threadIdx.x & 31;
    if (gw >= NN) return;
    const unsigned* row = d_bitmap + gw * 256;
    unsigned w[8]; int cnt = 0;
#pragma unroll
    for (int j = 0; j < 8; j++) { w[j] = row[lane * 8 + j]; cnt += __popc(w[j]); }
    int off = cnt;
#pragma unroll
    for (int d = 1; d < 32; d <<= 1) {
        int t = __shfl_up_sync(0xffffffffu, off, d);
        if (lane >= d) off += t;
    }
    off -= cnt;
    int pos = d_rowptr[gw] + off;
#pragma unroll
    for (int j = 0; j < 8; j++) {
        unsigned m = w[j];
        int base = (lane * 8 + j) << 5;
        while (m) {
            int b = __ffs(m) - 1;
            d_col[pos++] = base + b;
            m &= m - 1;
        }
    }
}

// ================= persistent ESN: all 64 steps, one kernel =================
// 256 threads / 8 warps (2m x 4n), warp tile 16x64. 2 CTAs per SM.
// h in fp32 registers; h's fp16 image in the resident smem A region.
// B (fp16 hi/lo) via 2-slot cp.async ring (wait_group 0; drain overlapped by peer CTA).

__device__ __forceinline__ void copyB_chunk(int c, uint32_t dstbase, int tid) {
#pragma unroll
    for (int i = 0; i < 4; i++) {
        int G = tid * 4 + i;          // 0..1023
        int row = G >> 2, q = G & 3;  // 256 rows x 4 x 16B granules
        size_t e = (size_t)row * 320 + c * 32 + q * 8;
        uint32_t d = dstbase + row * AROW + q * 16;
        CPA16(d,          (const char*)d_Bhi + e * 2);
        CPA16(d + BTYPE,  (const char*)d_Blo + e * 2);
    }
}

__device__ __forceinline__ void stage_x(const float* __restrict__ x, int t, int m0,
                                        int tid, char* smem) {
#pragma unroll
    for (int i = 0; i < 2; i++) {
        int g = tid * 2 + i;           // 0..511
        int row = g >> 4, q = g & 15;  // 32 rows x 16 float4
        float4 v = *(const float4*)(x + (size_t)(m0 + row) * (TT * DIN) + t * DIN + q * 4);
        union { __half hh[4]; uint2 u; } uh;
        uh.hh[0] = __float2half(v.x); uh.hh[1] = __float2half(v.y);
        uh.hh[2] = __float2half(v.z); uh.hh[3] = __float2half(v.w);
        int chunk = q >> 3, kc = (q & 7) * 4;
        uint32_t off = (uint32_t)chunk * ACH + row * AROW + kc * 2;
        *(uint2*)(smem + off) = uh.u;
    }
}

__global__ void __launch_bounds__(256, 2)
step_persist(const float* __restrict__ x)
{
    extern __shared__ __align__(128) char smem[];
    const int tid = threadIdx.x, wid = tid >> 5, lane = tid & 31;
    const int m0 = blockIdx.x * MTILE;
    const int warpM = (wid & 1) * 16;   // 2 m-groups of 16 rows
    const int warpN = (wid >> 1) * 64;  // 4 n-groups of 64 cols
    const uint32_t Ab = s2u(smem);
    const uint32_t Bb = Ab + AREG;

    // zero resident A region (h = 0 at t=0)
    for (int i = tid; i < AREG / 16; i += 256)
        *(uint4*)(smem + i * 16) = make_uint4(0, 0, 0, 0);

    float h[8][4], acc[8][4];
#pragma unroll
    for (int ni = 0; ni < 8; ni++)
#pragma unroll
        for (int q = 0; q < 4; q++) { h[ni][q] = 0.0f; acc[ni][q] = 0.0f; }

    // stage x for t=0; prime the B ring with chunk 0
    stage_x(x, 0, m0, tid, smem);
    copyB_chunk(0, Bb + 0 * BBUF, tid); CP_COMMIT;

#pragma unroll 1
    for (int t = 0; t < TT; t++) {
#pragma unroll 1
        for (int c = 0; c < 10; c++) {
            const int g = t * 10 + c;
            CP_WAIT0;          // chunk g landed
            __syncthreads();   // all warps done MMA(g-1) -> slot (g+1)%2 dead; chunk g visible
            if (g + 1 < TT * 10) {
                copyB_chunk((c + 1) % 10, Bb + (uint32_t)((g + 1) % NSLOT) * BBUF, tid);
                CP_COMMIT;
            }
            if (c == 2 && t + 1 < TT)
                stage_x(x, t + 1, m0, tid, smem);   // safe: x chunks 0,1 retired at c<=1

            const uint32_t Ac = Ab + (uint32_t)c * ACH;
            const uint32_t Bc = Bb + (uint32_t)(g % NSLOT) * BBUF;
#pragma unroll
            for (int ks = 0; ks < 2; ks++) {
                const int kb = ks * 32;  // byte offset of the k16 slice
                uint32_t ah[4];
                {
                    int row = warpM + (lane & 15);
                    uint32_t ad = Ac + row * AROW + kb + (lane >> 4) * 16;
                    LDSM4(ah, ad);
                }
#pragma unroll
                for (int nb = 0; nb < 4; nb++) {
                    int row = warpN + nb * 16 + ((lane >> 4) << 3) + (lane & 7);
                    uint32_t bd = Bc + row * AROW + kb + ((lane >> 3) & 1) * 16;
                    uint32_t bh[4], bl[4];
                    LDSM4(bh, bd);
                    LDSM4(bl, bd + BTYPE);
                    MMA16816(acc[nb * 2],     ah, bh[0], bh[1]);
                    MMA16816(acc[nb * 2],     ah, bl[0], bl[1]);
                    MMA16816(acc[nb * 2 + 1], ah, bh[2], bh[3]);
                    MMA16816(acc[nb * 2 + 1], ah, bl[2], bl[3]);
                }
            }
        }
        __syncthreads();  // all warps done reading the A region this step

        // ---- epilogue: h = 0.7h + 0.3 tanh(acc) ----
        if (t == TT - 1) {
#pragma unroll
            for (int ni = 0; ni < 8; ni++)
#pragma unroll
                for (int rr = 0; rr < 2; rr++) {
                    int row = m0 + warpM + (lane >> 2) + rr * 8;
                    int col = warpN + ni * 8 + (lane & 3) * 2;
                    float o0 = 0.7f * h[ni][rr * 2 + 0] + 0.3f * ftanh(acc[ni][rr * 2 + 0]);
                    float o1 = 0.7f * h[ni][rr * 2 + 1] + 0.3f * ftanh(acc[ni][rr * 2 + 1]);
                    *(float2*)&d_cat[(size_t)row * CATD + col] = make_float2(o0, o1);
                }
        } else {
#pragma unroll
            for (int ni = 0; ni < 8; ni++)
#pragma unroll
                for (int rr = 0; rr < 2; rr++) {
                    int rloc = warpM + (lane >> 2) + rr * 8;
                    int col = warpN + ni * 8 + (lane & 3) * 2;
                    float o0 = 0.7f * h[ni][rr * 2 + 0] + 0.3f * ftanh(acc[ni][rr * 2 + 0]);
                    float o1 = 0.7f * h[ni][rr * 2 + 1] + 0.3f * ftanh(acc[ni][rr * 2 + 1]);
                    h[ni][rr * 2 + 0] = o0;
                    h[ni][rr * 2 + 1] = o1;
                    acc[ni][rr * 2 + 0] = 0.0f;
                    acc[ni][rr * 2 + 1] = 0.0f;
                    union { __half hh[2]; uint32_t u; } uh;
                    uh.hh[0] = __float2half(o0);
                    uh.hh[1] = __float2half(o1);
                    // h occupies K range [64,320) => chunk 2 + col/32
                    uint32_t off = (uint32_t)(2 + (col >> 5)) * ACH + rloc * AROW + (col & 31) * 2;
                    *(uint32_t*)(smem + off) = uh.u;
                }
        }
        // next iteration's first in-loop __syncthreads publishes these h writes
        // before any ldmatrix consumes them (first h read is at c=2)
    }
}

// ---------------- SpMM hop ----------------
__global__ __launch_bounds__(256) void spmm_kernel(int hop) {
    int u = blockIdx.x;
    int r = threadIdx.x;
    int s = d_rowptr[u], e = d_rowptr[u + 1];
    const float* src = d_cat + (hop - 1) * RR + r;
    float acc = 0.0f;
    int i = s;
    for (; i + 4 <= e; i += 4) {
        int v0 = d_col[i], v1 = d_col[i + 1], v2 = d_col[i + 2], v3 = d_col[i + 3];
        float x0 = src[(size_t)v0 * CATD];
        float x1 = src[(size_t)v1 * CATD];
        float x2 = src[(size_t)v2 * CATD];
        float x3 = src[(size_t)v3 * CATD];
        acc += d_dinv[v0] * x0 + d_dinv[v1] * x1 + d_dinv[v2] * x2 + d_dinv[v3] * x3;
    }
    for (; i < e; i++) {
        int v = d_col[i];
        acc += d_dinv[v] * src[(size_t)v * CATD];
    }
    d_cat[u * CATD + hop * RR + r] = d_dinv[u] * acc;
}

// ---------------- readout (fp32 SIMT) ----------------
__global__ __launch_bounds__(256) void readout_kernel(
    const float* __restrict__ W1, const float* __restrict__ b1,
    const float* __restrict__ W2, const float* __restrict__ b2,
    const float* __restrict__ gamma, const float* __restrict__ beta,
    float* __restrict__ out)
{
    __shared__ float As1[16][64 + 4];
    __shared__ float Bs1[16][128 + 4];
    __shared__ float z1t[128][64 + 4];

    int tid = threadIdx.x;
    int n0 = blockIdx.x * 64;

    int rg = tid >> 5;
    int cg = tid & 31;
    float acc[8][4];
#pragma unroll
    for (int i = 0; i < 8; i++)
#pragma unroll
        for (int j = 0; j < 4; j++) acc[i][j] = 0.0f;

    int lm = tid >> 2;
    int lka = (tid & 3) * 4;
    int lj = tid >> 1;
    int lkb = (tid & 1) * 8;
    const float* arow = d_cat + (n0 + lm) * CATD;
    const float* brow = W1 + lj * CATD;

#pragma unroll 1
    for (int kt = 0; kt < 64; kt++) {
        int k0 = kt * 16;
        float4 va = *(const float4*)(arow + k0 + lka);
        As1[lka + 0][lm] = va.x; As1[lka + 1][lm] = va.y;
        As1[lka + 2][lm] = va.z; As1[lka + 3][lm] = va.w;
        float4 vb0 = *(const float4*)(brow + k0 + lkb);
        float4 vb1 = *(const float4*)(brow + k0 + lkb + 4);
        Bs1[lkb + 0][lj] = vb0.x; Bs1[lkb + 1][lj] = vb0.y;
        Bs1[lkb + 2][lj] = vb0.z; Bs1[lkb + 3][lj] = vb0.w;
        Bs1[lkb + 4][lj] = vb1.x; Bs1[lkb + 5][lj] = vb1.y;
        Bs1[lkb + 6][lj] = vb1.z; Bs1[lkb + 7][lj] = vb1.w;
        __syncthreads();
#pragma unroll
        for (int kk = 0; kk < 16; kk++) {
            float4 a0 = *(const float4*)&As1[kk][rg * 8];
            float4 a1 = *(const float4*)&As1[kk][rg * 8 + 4];
            float4 b4 = *(const float4*)&Bs1[kk][cg * 4];
            float av[8] = {a0.x, a0.y, a0.z, a0.w, a1.x, a1.y, a1.z, a1.w};
            float bv[4] = {b4.x, b4.y, b4.z, b4.w};
#pragma unroll
            for (int i = 0; i < 8; i++)
#pragma unroll
                for (int j = 0; j < 4; j++) acc[i][j] += av[i] * bv[j];
        }
        __syncthreads();
    }

#pragma unroll
    for (int i = 0; i < 8; i++) {
#pragma unroll
        for (int j = 0; j < 4; j++) {
            int col = cg * 4 + j;
            int row = rg * 8 + i;
            float v = acc[i][j] + b1[col];
            float g = 0.5f * v * (1.0f + erff(v * 0.70710678118654752f));
            z1t[col][row] = g;
        }
    }
    __syncthreads();

    int rg2 = tid >> 4;
    int cg2 = tid & 15;
    float acc2[4][4];
#pragma unroll
    for (int i = 0; i < 4; i++)
#pragma unroll
        for (int j = 0; j < 4; j++) acc2[i][j] = 0.0f;

#pragma unroll 4
    for (int k = 0; k < 128; k++) {
        float4 a = *(const float4*)&z1t[k][rg2 * 4];
        float av[4] = {a.x, a.y, a.z, a.w};
#pragma unroll
        for (int j = 0; j < 4; j++) {
            float b = __ldg(&W2[(cg2 * 4 + j) * 128 + k]);
#pragma unroll
            for (int i = 0; i < 4; i++) acc2[i][j] += av[i] * b;
        }
    }

    float vals[4][4];
#pragma unroll
    for (int i = 0; i < 4; i++)
#pragma unroll
        for (int j = 0; j < 4; j++) vals[i][j] = acc2[i][j] + b2[cg2 * 4 + j];

    float mean[4], var[4];
#pragma unroll
    for (int i = 0; i < 4; i++) {
        float s = vals[i][0] + vals[i][1] + vals[i][2] + vals[i][3];
#pragma unroll
        for (int o = 8; o; o >>= 1) s += __shfl_xor_sync(0xffffffffu, s, o);
        mean[i] = s * (1.0f / 64.0f);
    }
#pragma unroll
    for (int i = 0; i < 4; i++) {
        float s = 0.0f;
#pragma unroll
        for (int j = 0; j < 4; j++) {
            float d = vals[i][j] - mean[i];
            s += d * d;
        }
#pragma unroll
        for (int o = 8; o; o >>= 1) s += __shfl_xor_sync(0xffffffffu, s, o);
        var[i] = s * (1.0f / 64.0f);
    }

#pragma unroll
    for (int i = 0; i < 4; i++) {
        int node = n0 + rg2 * 4 + i;
        float inv = 1.0f / sqrtf(var[i] + 1e-5f);
        float4 o;
        float g0 = gamma[cg2 * 4 + 0], g1 = gamma[cg2 * 4 + 1];
        float g2 = gamma[cg2 * 4 + 2], g3 = gamma[cg2 * 4 + 3];
        float be0 = beta[cg2 * 4 + 0], be1 = beta[cg2 * 4 + 1];
        float be2 = beta[cg2 * 4 + 2], be3 = beta[cg2 * 4 + 3];
        o.x = (vals[i][0] - mean[i]) * inv * g0 + be0;
        o.y = (vals[i][1] - mean[i]) * inv * g1 + be1;
        o.z = (vals[i][2] - mean[i]) * inv * g2 + be2;
        o.w = (vals[i][3] - mean[i]) * inv * g3 + be3;
        *(float4*)&out[node * DOUT + cg2 * 4] = o;
    }
}

// ---------------- launch ----------------
extern "C" void kernel_launch(void* const* d_in, const int* in_sizes, int n_in,
                              void* d_out, int out_size) {
    const float* x     = (const float*)d_in[0];
    const void*  ei    = d_in[1];
    const float* Win   = (const float*)d_in[2];
    const float* Wres  = (const float*)d_in[3];
    const float* W1    = (const float*)d_in[4];
    const float* b1    = (const float*)d_in[5];
    const float* W2    = (const float*)d_in[6];
    const float* b2    = (const float*)d_in[7];
    const float* gamma = (const float*)d_in[8];
    const float* beta  = (const float*)d_in[9];
    float* out = (float*)d_out;

    (void)cudaFuncSetAttribute(step_persist, cudaFuncAttributeMaxDynamicSharedMemorySize, STEP_SMEM);

    detect_kernel<<<1, 32>>>((const unsigned*)ei);
    zero_kernel<<<4096, 512>>>();
    wconv_kernel<<<320, 256>>>(Win, Wres);
    pass1_kernel<<<1024, 256>>>(ei);
    degdinv_kernel<<<1024, 256>>>();
    scan_kernel<<<1, 1024>>>();
    extract_kernel<<<1024, 256>>>();

    step_persist<<<NN / MTILE, 256, STEP_SMEM>>>(x);

    for (int hop = 1; hop <= 3; hop++)
        spmm_kernel<<<NN, 256>>>(hop);

    readout_kernel<<<128, 256>>>(W1, b1, W2, b2, gamma, beta, out);
}

// round 17
// speedup vs baseline: 2.1774x; 2.1774x over previous
#include <cuda_runtime.h>
#include <cuda_fp16.h>
#include <stdint.h>
#include <math.h>

// Problem constants
#define NN 8192      // nodes
#define TT 64        // timesteps
#define DIN 64       // input dim
#define RR 256       // reservoir dim
#define EE 131072    // edges
#define DOUT 64
#define CATD 1024    // (K+1)*R

// persistent step kernel tiling: CTA = 64 rows x 256 cols, K=320 in 10 chunks of 32.
// PURE fp16 single-product scheme: A (x|h) fp16, B (weights) fp16.
// 512 threads / 16 warps: warp tile 32x32 (4 warps per SMSP).
#define MTILE 64
#define AROW 80                      // smem bytes per 32-fp16 row (64B data + 16B pad)
#define ACH  (MTILE * AROW)          // 5120 B  (one A chunk)
#define AREG (10 * ACH)              // 51200 B resident A region
#define BBUF (256 * AROW)            // 20480 B per slot (single fp16 type)
#define NSLOT 3
#define STEP_SMEM (AREG + NSLOT * BBUF)  // 112640 B

// ---------------- device scratch (static allocations only) ----------------
__device__ __align__(16) __half d_Bw[RR * 320];    // [Win|Wres] fp16, [256][320]
__device__ unsigned d_bitmap[NN * (NN / 32)];
__device__ int      d_deg[NN];
__device__ int      d_rowptr[NN + 1];
__device__ int      d_col[2 * EE];
__device__ float    d_dinv[NN];
__device__ float    d_cat[NN * CATD];
__device__ int      d_is64;

// ================= PTX helpers (sm_80-compatible only) =================
__device__ __forceinline__ uint32_t s2u(const void* p) {
    uint32_t a;
    asm("{ .reg .u64 t; cvta.to.shared.u64 t, %1; cvt.u32.u64 %0, t; }" : "=r"(a) : "l"(p));
    return a;
}
#define LDSM4(r, addr) \
    asm volatile("ldmatrix.sync.aligned.m8n8.x4.shared.b16 {%0,%1,%2,%3}, [%4];" \
        : "=r"((r)[0]), "=r"((r)[1]), "=r"((r)[2]), "=r"((r)[3]) : "r"(addr))

#define MMA16816(d, a, b0, b1) \
    asm volatile("mma.sync.aligned.m16n8k16.row.col.f32.f16.f16.f32 " \
        "{%0,%1,%2,%3}, {%4,%5,%6,%7}, {%8,%9}, {%0,%1,%2,%3};" \
        : "+f"((d)[0]), "+f"((d)[1]), "+f"((d)[2]), "+f"((d)[3]) \
        : "r"((a)[0]), "r"((a)[1]), "r"((a)[2]), "r"((a)[3]), "r"(b0), "r"(b1))

#define CPA16(dst, src) \
    asm volatile("cp.async.cg.shared.global [%0], [%1], 16;" :: "r"(dst), "l"(src) : "memory")
#define CP_COMMIT asm volatile("cp.async.commit_group;" ::: "memory")
#define CP_WAIT1  asm volatile("cp.async.wait_group 1;" ::: "memory")

__device__ __forceinline__ float ftanh(float v) {
    float a = fabsf(v);
    float e = __expf(-2.0f * a);
    float r = __fdividef(1.0f - e, 1.0f + e);
    return copysignf(r, v);
}

// ---------------- dtype detection for edge_index (int32 vs int64) ----------------
__global__ void detect_kernel(const unsigned* __restrict__ w) {
    if (threadIdx.x == 0) {
        int f = 1;
        for (int i = 0; i < 64; i++) {
            if (w[2 * i + 1] != 0u) { f = 0; break; }
        }
        d_is64 = f;
    }
}

// ---------------- zero bitmap ----------------
__global__ void zero_kernel() {
    int i = blockIdx.x * blockDim.x + threadIdx.x;  // 2097152 threads
    d_bitmap[i] = 0u;
}

// ---------------- weight conversion to fp16 ----------------
__global__ void wconv_kernel(const float* __restrict__ Win, const float* __restrict__ Wres) {
    int i = blockIdx.x * blockDim.x + threadIdx.x;
    if (i >= 256 * 320) return;
    int r = i / 320, k = i % 320;
    float v = (k < DIN) ? Win[r * DIN + k] : Wres[r * RR + (k - DIN)];
    d_Bw[i] = __float2half(v);
}

// ---------------- build binary adjacency bitmap ----------------
__global__ void pass1_kernel(const void* __restrict__ ei) {
    int i = blockIdx.x * blockDim.x + threadIdx.x;
    if (i >= 2 * EE) return;
    int u, v;
    if (d_is64) {
        const long long* p = (const long long*)ei;
        if (i < EE) { u = (int)p[i]; v = (int)p[EE + i]; }
        else        { u = (int)p[i]; v = (int)p[i - EE]; }
    } else {
        const int* p = (const int*)ei;
        if (i < EE) { u = p[i]; v = p[EE + i]; }
        else        { u = p[i]; v = p[i - EE]; }
    }
    atomicOr(&d_bitmap[(u << 8) + (v >> 5)], 1u << (v & 31));
}

// ---------------- degree + dinv ----------------
__global__ void degdinv_kernel() {
    int gw = (blockIdx.x * blockDim.x + threadIdx.x) >> 5;
    int lane = threadIdx.x & 31;
    if (gw >= NN) return;
    const unsigned* row = d_bitmap + gw * 256;
    int c = 0;
#pragma unroll
    for (int j = 0; j < 8; j++) c += __popc(row[lane * 8 + j]);
#pragma unroll
    for (int o = 16; o; o >>= 1) c += __shfl_xor_sync(0xffffffffu, c, o);
    if (lane == 0) {
        d_deg[gw] = c;
        d_dinv[gw] = (c > 0) ? fminf(1e6f, 1.0f / sqrtf((float)c)) : 0.0f;
    }
}

// ---------------- exclusive scan -> rowptr ----------------
__global__ void scan_kernel() {
    __shared__ int s[1024];
    int tid = threadIdx.x;
    int loc[8]; int sum = 0;
#pragma unroll
    for (int j = 0; j < 8; j++) { loc[j] = d_deg[tid * 8 + j]; sum += loc[j]; }
    s[tid] = sum;
    __syncthreads();
    for (int off = 1; off < 1024; off <<= 1) {
        int t = 0;
        if (tid >= off) t = s[tid - off];
        __syncthreads();
        s[tid] += t;
        __syncthreads();
    }
    int run = (tid == 0) ? 0 : s[tid - 1];
    if (tid == 0) d_rowptr[0] = 0;
#pragma unroll
    for (int j = 0; j < 8; j++) { run += loc[j]; d_rowptr[tid * 8 + j + 1] = run; }
}

// ---------------- extract CSR cols ----------------
__global__ void extract_kernel() {
    int gw = (blockIdx.x * blockDim.x + threadIdx.x) >> 5;
    int lane = threadIdx.x & 31;
    if (gw >= NN) return;
    const unsigned* row = d_bitmap + gw * 256;
    unsigned w[8]; int cnt = 0;
#pragma unroll
    for (int j = 0; j < 8; j++) { w[j] = row[lane * 8 + j]; cnt += __popc(w[j]); }
    int off = cnt;
#pragma unroll
    for (int d = 1; d < 32; d <<= 1) {
        int t = __shfl_up_sync(0xffffffffu, off, d);
        if (lane >= d) off += t;
    }
    off -= cnt;
    int pos = d_rowptr[gw] + off;
#pragma unroll
    for (int j = 0; j < 8; j++) {
        unsigned m = w[j];
        int base = (lane * 8 + j) << 5;
        while (m) {
            int b = __ffs(m) - 1;
            d_col[pos++] = base + b;
            m &= m - 1;
        }
    }
}

// ================= persistent ESN: all 64 steps, one kernel =================
// 512 threads, 16 warps (2m x 8n), warp tile 32x32. h in fp32 registers; h's
// fp16 image in the resident smem A region. B (fp16) via 3-slot cp.async ring.

__device__ __forceinline__ void copyB_chunk(int c, uint32_t dstbase, int tid) {
#pragma unroll
    for (int i = 0; i < 2; i++) {
        int G = tid * 2 + i;          // 0..1023
        int row = G >> 2, q = G & 3;  // 256 rows x 4 x 16B granules
        size_t e = (size_t)row * 320 + c * 32 + q * 8;
        CPA16(dstbase + row * AROW + q * 16, (const char*)d_Bw + e * 2);
    }
}

__device__ __forceinline__ void stage_x(const float* __restrict__ x, int t, int m0,
                                        int tid, char* smem) {
#pragma unroll
    for (int i = 0; i < 2; i++) {
        int g = tid * 2 + i;           // 0..1023
        int row = g >> 4, q = g & 15;  // 64 rows x 16 float4
        float4 v = *(const float4*)(x + (size_t)(m0 + row) * (TT * DIN) + t * DIN + q * 4);
        union { __half hh[4]; uint2 u; } uh;
        uh.hh[0] = __float2half(v.x); uh.hh[1] = __float2half(v.y);
        uh.hh[2] = __float2half(v.z); uh.hh[3] = __float2half(v.w);
        int chunk = q >> 3, kc = (q & 7) * 4;
        uint32_t off = (uint32_t)chunk * ACH + row * AROW + kc * 2;
        *(uint2*)(smem + off) = uh.u;
    }
}

__global__ void __launch_bounds__(512)
step_persist(const float* __restrict__ x)
{
    extern __shared__ __align__(128) char smem[];
    const int tid = threadIdx.x, wid = tid >> 5, lane = tid & 31;
    const int m0 = blockIdx.x * MTILE;
    const int warpM = (wid & 1) * 32;   // 2 m-groups of 32 rows
    const int warpN = (wid >> 1) * 32;  // 8 n-groups of 32 cols
    const uint32_t Ab = s2u(smem);
    const uint32_t Bb = Ab + AREG;

    // zero resident A region (h = 0 at t=0)
    for (int i = tid; i < AREG / 16; i += 512)
        *(uint4*)(smem + i * 16) = make_uint4(0, 0, 0, 0);

    float h[2][4][4], acc[2][4][4];
#pragma unroll
    for (int mi = 0; mi < 2; mi++)
#pragma unroll
        for (int ni = 0; ni < 4; ni++)
#pragma unroll
            for (int q = 0; q < 4; q++) { h[mi][ni][q] = 0.0f; acc[mi][ni][q] = 0.0f; }

    // stage x for t=0; prime the B ring with chunks 0 and 1
    stage_x(x, 0, m0, tid, smem);
    copyB_chunk(0, Bb + 0 * BBUF, tid); CP_COMMIT;
    copyB_chunk(1, Bb + 1 * BBUF, tid); CP_COMMIT;

#pragma unroll 1
    for (int t = 0; t < TT; t++) {
#pragma unroll 1
        for (int c = 0; c < 10; c++) {
            const int g = t * 10 + c;
            CP_WAIT1;          // uniform group counting -> chunk g guaranteed landed
            __syncthreads();   // all warps done MMA(g-1) -> slot (g+2)%3 dead; chunk g visible
            if (g + 2 < TT * 10)
                copyB_chunk((c + 2) % 10, Bb + (uint32_t)((g + 2) % NSLOT) * BBUF, tid);
            CP_COMMIT;         // unconditional: empty tail groups keep counts uniform
            if (c == 2 && t + 1 < TT)
                stage_x(x, t + 1, m0, tid, smem);   // safe: x chunks 0,1 retired at c<=1

            const uint32_t Ac = Ab + (uint32_t)c * ACH;
            const uint32_t Bc = Bb + (uint32_t)(g % NSLOT) * BBUF;
#pragma unroll
            for (int ks = 0; ks < 2; ks++) {
                const int kb = ks * 32;  // byte offset of the k16 slice
                uint32_t ah[2][4];
#pragma unroll
                for (int mi = 0; mi < 2; mi++) {
                    int row = warpM + mi * 16 + (lane & 15);
                    uint32_t ad = Ac + row * AROW + kb + (lane >> 4) * 16;
                    LDSM4(ah[mi], ad);
                }
#pragma unroll
                for (int nb = 0; nb < 2; nb++) {
                    int row = warpN + nb * 16 + ((lane >> 4) << 3) + (lane & 7);
                    uint32_t bd = Bc + row * AROW + kb + ((lane >> 3) & 1) * 16;
                    uint32_t bh[4];
                    LDSM4(bh, bd);
#pragma unroll
                    for (int mi = 0; mi < 2; mi++) {
                        MMA16816(acc[mi][nb * 2],     ah[mi], bh[0], bh[1]);
                        MMA16816(acc[mi][nb * 2 + 1], ah[mi], bh[2], bh[3]);
                    }
                }
            }
        }
        __syncthreads();  // all warps done reading the A region this step

        // ---- epilogue: h = 0.7h + 0.3 tanh(acc) ----
        if (t == TT - 1) {
#pragma unroll
            for (int mi = 0; mi < 2; mi++)
#pragma unroll
                for (int ni = 0; ni < 4; ni++)
#pragma unroll
                    for (int rr = 0; rr < 2; rr++) {
                        int row = m0 + warpM + mi * 16 + (lane >> 2) + rr * 8;
                        int col = warpN + ni * 8 + (lane & 3) * 2;
                        float o0 = 0.7f * h[mi][ni][rr * 2 + 0] + 0.3f * ftanh(acc[mi][ni][rr * 2 + 0]);
                        float o1 = 0.7f * h[mi][ni][rr * 2 + 1] + 0.3f * ftanh(acc[mi][ni][rr * 2 + 1]);
                        *(float2*)&d_cat[(size_t)row * CATD + col] = make_float2(o0, o1);
                    }
        } else {
#pragma unroll
            for (int mi = 0; mi < 2; mi++)
#pragma unroll
                for (int ni = 0; ni < 4; ni++)
#pragma unroll
                    for (int rr = 0; rr < 2; rr++) {
                        int rloc = warpM + mi * 16 + (lane >> 2) + rr * 8;
                        int col = warpN + ni * 8 + (lane & 3) * 2;
                        float o0 = 0.7f * h[mi][ni][rr * 2 + 0] + 0.3f * ftanh(acc[mi][ni][rr * 2 + 0]);
                        float o1 = 0.7f * h[mi][ni][rr * 2 + 1] + 0.3f * ftanh(acc[mi][ni][rr * 2 + 1]);
                        h[mi][ni][rr * 2 + 0] = o0;
                        h[mi][ni][rr * 2 + 1] = o1;
                        acc[mi][ni][rr * 2 + 0] = 0.0f;
                        acc[mi][ni][rr * 2 + 1] = 0.0f;
                        union { __half hh[2]; uint32_t u; } uh;
                        uh.hh[0] = __float2half(o0);
                        uh.hh[1] = __float2half(o1);
                        // h occupies K range [64,320) => chunk 2 + col/32
                        uint32_t off = (uint32_t)(2 + (col >> 5)) * ACH + rloc * AROW + (col & 31) * 2;
                        *(uint32_t*)(smem + off) = uh.u;
                    }
        }
        // next iteration's first in-loop __syncthreads publishes these h writes
        // before any ldmatrix consumes them (first h read is at c=2)
    }
}

// ---------------- SpMM hop ----------------
__global__ __launch_bounds__(256) void spmm_kernel(int hop) {
    int u = blockIdx.x;
    int r = threadIdx.x;
    int s = d_rowptr[u], e = d_rowptr[u + 1];
    const float* src = d_cat + (hop - 1) * RR + r;
    float acc = 0.0f;
    int i = s;
    for (; i + 4 <= e; i += 4) {
        int v0 = d_col[i], v1 = d_col[i + 1], v2 = d_col[i + 2], v3 = d_col[i + 3];
        float x0 = src[(size_t)v0 * CATD];
        float x1 = src[(size_t)v1 * CATD];
        float x2 = src[(size_t)v2 * CATD];
        float x3 = src[(size_t)v3 * CATD];
        acc += d_dinv[v0] * x0 + d_dinv[v1] * x1 + d_dinv[v2] * x2 + d_dinv[v3] * x3;
    }
    for (; i < e; i++) {
        int v = d_col[i];
        acc += d_dinv[v] * src[(size_t)v * CATD];
    }
    d_cat[u * CATD + hop * RR + r] = d_dinv[u] * acc;
}

// ---------------- readout (fp32 SIMT) ----------------
__global__ __launch_bounds__(256) void readout_kernel(
    const float* __restrict__ W1, const float* __restrict__ b1,
    const float* __restrict__ W2, const float* __restrict__ b2,
    const float* __restrict__ gamma, const float* __restrict__ beta,
    float* __restrict__ out)
{
    __shared__ float As1[16][64 + 4];
    __shared__ float Bs1[16][128 + 4];
    __shared__ float z1t[128][64 + 4];

    int tid = threadIdx.x;
    int n0 = blockIdx.x * 64;

    int rg = tid >> 5;
    int cg = tid & 31;
    float acc[8][4];
#pragma unroll
    for (int i = 0; i < 8; i++)
#pragma unroll
        for (int j = 0; j < 4; j++) acc[i][j] = 0.0f;

    int lm = tid >> 2;
    int lka = (tid & 3) * 4;
    int lj = tid >> 1;
    int lkb = (tid & 1) * 8;
    const float* arow = d_cat + (n0 + lm) * CATD;
    const float* brow = W1 + lj * CATD;

#pragma unroll 1
    for (int kt = 0; kt < 64; kt++) {
        int k0 = kt * 16;
        float4 va = *(const float4*)(arow + k0 + lka);
        As1[lka + 0][lm] = va.x; As1[lka + 1][lm] = va.y;
        As1[lka + 2][lm] = va.z; As1[lka + 3][lm] = va.w;
        float4 vb0 = *(const float4*)(brow + k0 + lkb);
        float4 vb1 = *(const float4*)(brow + k0 + lkb + 4);
        Bs1[lkb + 0][lj] = vb0.x; Bs1[lkb + 1][lj] = vb0.y;
        Bs1[lkb + 2][lj] = vb0.z; Bs1[lkb + 3][lj] = vb0.w;
        Bs1[lkb + 4][lj] = vb1.x; Bs1[lkb + 5][lj] = vb1.y;
        Bs1[lkb + 6][lj] = vb1.z; Bs1[lkb + 7][lj] = vb1.w;
        __syncthreads();
#pragma unroll
        for (int kk = 0; kk < 16; kk++) {
            float4 a0 = *(const float4*)&As1[kk][rg * 8];
            float4 a1 = *(const float4*)&As1[kk][rg * 8 + 4];
            float4 b4 = *(const float4*)&Bs1[kk][cg * 4];
            float av[8] = {a0.x, a0.y, a0.z, a0.w, a1.x, a1.y, a1.z, a1.w};
            float bv[4] = {b4.x, b4.y, b4.z, b4.w};
#pragma unroll
            for (int i = 0; i < 8; i++)
#pragma unroll
                for (int j = 0; j < 4; j++) acc[i][j] += av[i] * bv[j];
        }
        __syncthreads();
    }

#pragma unroll
    for (int i = 0; i < 8; i++) {
#pragma unroll
        for (int j = 0; j < 4; j++) {
            int col = cg * 4 + j;
            int row = rg * 8 + i;
            float v = acc[i][j] + b1[col];
            float g = 0.5f * v * (1.0f + erff(v * 0.70710678118654752f));
            z1t[col][row] = g;
        }
    }
    __syncthreads();

    int rg2 = tid >> 4;
    int cg2 = tid & 15;
    float acc2[4][4];
#pragma unroll
    for (int i = 0; i < 4; i++)
#pragma unroll
        for (int j = 0; j < 4; j++) acc2[i][j] = 0.0f;

#pragma unroll 4
    for (int k = 0; k < 128; k++) {
        float4 a = *(const float4*)&z1t[k][rg2 * 4];
        float av[4] = {a.x, a.y, a.z, a.w};
#pragma unroll
        for (int j = 0; j < 4; j++) {
            float b = __ldg(&W2[(cg2 * 4 + j) * 128 + k]);
#pragma unroll
            for (int i = 0; i < 4; i++) acc2[i][j] += av[i] * b;
        }
    }

    float vals[4][4];
#pragma unroll
    for (int i = 0; i < 4; i++)
#pragma unroll
        for (int j = 0; j < 4; j++) vals[i][j] = acc2[i][j] + b2[cg2 * 4 + j];

    float mean[4], var[4];
#pragma unroll
    for (int i = 0; i < 4; i++) {
        float s = vals[i][0] + vals[i][1] + vals[i][2] + vals[i][3];
#pragma unroll
        for (int o = 8; o; o >>= 1) s += __shfl_xor_sync(0xffffffffu, s, o);
        mean[i] = s * (1.0f / 64.0f);
    }
#pragma unroll
    for (int i = 0; i < 4; i++) {
        float s = 0.0f;
#pragma unroll
        for (int j = 0; j < 4; j++) {
            float d = vals[i][j] - mean[i];
            s += d * d;
        }
#pragma unroll
        for (int o = 8; o; o >>= 1) s += __shfl_xor_sync(0xffffffffu, s, o);
        var[i] = s * (1.0f / 64.0f);
    }

#pragma unroll
    for (int i = 0; i < 4; i++) {
        int node = n0 + rg2 * 4 + i;
        float inv = 1.0f / sqrtf(var[i] + 1e-5f);
        float4 o;
        float g0 = gamma[cg2 * 4 + 0], g1 = gamma[cg2 * 4 + 1];
        float g2 = gamma[cg2 * 4 + 2], g3 = gamma[cg2 * 4 + 3];
        float be0 = beta[cg2 * 4 + 0], be1 = beta[cg2 * 4 + 1];
        float be2 = beta[cg2 * 4 + 2], be3 = beta[cg2 * 4 + 3];
        o.x = (vals[i][0] - mean[i]) * inv * g0 + be0;
        o.y = (vals[i][1] - mean[i]) * inv * g1 + be1;
        o.z = (vals[i][2] - mean[i]) * inv * g2 + be2;
        o.w = (vals[i][3] - mean[i]) * inv * g3 + be3;
        *(float4*)&out[node * DOUT + cg2 * 4] = o;
    }
}

// ---------------- launch ----------------
extern "C" void kernel_launch(void* const* d_in, const int* in_sizes, int n_in,
                              void* d_out, int out_size) {
    const float* x     = (const float*)d_in[0];
    const void*  ei    = d_in[1];
    const float* Win   = (const float*)d_in[2];
    const float* Wres  = (const float*)d_in[3];
    const float* W1    = (const float*)d_in[4];
    const float* b1    = (const float*)d_in[5];
    const float* W2    = (const float*)d_in[6];
    const float* b2    = (const float*)d_in[7];
    const float* gamma = (const float*)d_in[8];
    const float* beta  = (const float*)d_in[9];
    float* out = (float*)d_out;

    (void)cudaFuncSetAttribute(step_persist, cudaFuncAttributeMaxDynamicSharedMemorySize, STEP_SMEM);

    detect_kernel<<<1, 32>>>((const unsigned*)ei);
    zero_kernel<<<4096, 512>>>();
    wconv_kernel<<<320, 256>>>(Win, Wres);
    pass1_kernel<<<1024, 256>>>(ei);
    degdinv_kernel<<<1024, 256>>>();
    scan_kernel<<<1, 1024>>>();
    extract_kernel<<<1024, 256>>>();

    step_persist<<<NN / MTILE, 512, STEP_SMEM>>>(x);

    for (int hop = 1; hop <= 3; hop++)
        spmm_kernel<<<NN, 256>>>(hop);

    readout_kernel<<<128, 256>>>(W1, b1, W2, b2, gamma, beta, out);
}